// round 5
// baseline (speedup 1.0000x reference)
#include <cuda_runtime.h>
#include <cstdint>

#define B_  2
#define N_  1024
#define M_  1024
#define H_  128
#define G_  128          // single wave (<=148 SMs)
#define SCALE_ (1.0f / 6.964404506368992f)  // 1 / 128^0.4

__device__ float g_ks[B_ * M_];          // scaled logits
__device__ unsigned g_count;             // zero-init; monotonic ticket barrier

__device__ __forceinline__ uint32_t smem_u32(const void* p) {
    uint32_t a;
    asm("{ .reg .u64 t; cvta.to.shared.u64 t, %1; cvt.u32.u64 %0, t; }"
        : "=r"(a) : "l"(p));
    return a;
}

__global__ __launch_bounds__(1024) void k_fused(const float* __restrict__ keys,
                                                const float* __restrict__ values,
                                                const float* __restrict__ W,
                                                const float* __restrict__ bias,
                                                float* __restrict__ out) {
    const int tid = threadIdx.x;
    const int lane = tid & 31;
    const int warp = tid >> 5;
    const int blk = blockIdx.x;

    // 32 KB pool: phase1 = part4[32][32] float4 (16KB); phase4 = 2 x 16KB out tiles
    __shared__ float4 sh_pool[2048];
    __shared__ float4 sh_wcol4[H_ / 4];
    __shared__ float sh_s[M_];           // softmax row (4 KB)
    __shared__ float sh_bsum;
    __shared__ float red[32];
    __shared__ float red2[32];

    // ---------------- Phase 1: wcol = colsum(W), bsum = sum(bias) ----------
    {
        const int c4 = tid & 31;         // float4 column 0..31
        const int grp = tid >> 5;        // 32 groups x 4 rows
        const float4* W4 = reinterpret_cast<const float4*>(W);
        float4 a = W4[(grp * 4 + 0) * 32 + c4];
        float4 b1 = W4[(grp * 4 + 1) * 32 + c4];
        float4 c1 = W4[(grp * 4 + 2) * 32 + c4];
        float4 d1 = W4[(grp * 4 + 3) * 32 + c4];
        sh_pool[grp * 32 + c4] = make_float4((a.x + b1.x) + (c1.x + d1.x),
                                             (a.y + b1.y) + (c1.y + d1.y),
                                             (a.z + b1.z) + (c1.z + d1.z),
                                             (a.w + b1.w) + (c1.w + d1.w));
    }
    if (warp == 1) {                     // bias sum in warp 1 (warp 0 busy)
        float bs = bias[lane] + bias[lane + 32] + bias[lane + 64] + bias[lane + 96];
        #pragma unroll
        for (int o = 16; o > 0; o >>= 1) bs += __shfl_xor_sync(0xffffffffu, bs, o);
        if (lane == 0) sh_bsum = bs;
    }
    __syncthreads();
    if (tid < 32) {                      // final colsum reduce
        float4 s = make_float4(0.f, 0.f, 0.f, 0.f);
        #pragma unroll
        for (int g = 0; g < 32; ++g) {
            float4 p = sh_pool[g * 32 + tid];
            s.x += p.x; s.y += p.y; s.z += p.z; s.w += p.w;
        }
        sh_wcol4[tid] = s;
    }
    __syncthreads();

    // ---------------- Phase 2: 16 key-row dots per block --------------------
    if (warp < 16) {
        const int row = blk * 16 + warp;
        const float4 k4 = reinterpret_cast<const float4*>(keys)[row * 32 + lane];
        const float4 w4 = sh_wcol4[lane];
        float acc = k4.x * w4.x + k4.y * w4.y + k4.z * w4.z + k4.w * w4.w;
        #pragma unroll
        for (int o = 16; o > 0; o >>= 1) acc += __shfl_xor_sync(0xffffffffu, acc, o);
        if (lane == 0) __stcg(&g_ks[row], SCALE_ * (acc + sh_bsum));
    }

    // ---------------- Grid barrier (monotonic ticket, replay-safe) ----------
    __syncthreads();
    if (tid == 0) {
        __threadfence();
        const unsigned ticket = atomicAdd(&g_count, 1u);
        const unsigned target = (ticket / G_ + 1u) * G_;
        while (*((volatile unsigned*)&g_count) < target) { }
        __threadfence();
    }
    __syncthreads();

    // ---------------- Phase 3: softmax (redundant per block) ----------------
    const int b = blk >> 6;              // 64 blocks per batch
    const float x = __ldcg(&g_ks[b * M_ + tid]);

    float m = x;
    #pragma unroll
    for (int o = 16; o > 0; o >>= 1) m = fmaxf(m, __shfl_xor_sync(0xffffffffu, m, o));
    if (lane == 0) red[warp] = m;
    __syncthreads();
    if (tid < 32) {
        float v = red[tid];
        #pragma unroll
        for (int o = 16; o > 0; o >>= 1) v = fmaxf(v, __shfl_xor_sync(0xffffffffu, v, o));
        red[tid] = v;
    }
    __syncthreads();
    const float e = __expf(x - red[0]);

    float s = e;
    #pragma unroll
    for (int o = 16; o > 0; o >>= 1) s += __shfl_xor_sync(0xffffffffu, s, o);
    if (lane == 0) red2[warp] = s;
    __syncthreads();
    if (tid < 32) {
        float v = red2[tid];
        #pragma unroll
        for (int o = 16; o > 0; o >>= 1) v += __shfl_xor_sync(0xffffffffu, v, o);
        red2[tid] = v;
    }
    __syncthreads();
    sh_s[tid] = e / red2[0];
    __syncthreads();

    // ---------------- Phase 4: 16 output rows via TMA bulk stores -----------
    // 4 iterations x (4 rows = 16 KB tile); double-buffered in sh_pool.
    const int r = tid >> 8;              // 0..3 row within tile
    const int col = tid & 255;           // float4 column
    const float4 s4 = reinterpret_cast<const float4*>(sh_s)[col];
    const int row0 = blk * 16;

    #pragma unroll
    for (int i = 0; i < 4; ++i) {
        float4* buf = sh_pool + (i & 1) * 1024;   // 1024 float4 = 16 KB
        if (i >= 2) {                             // buffer reuse: drain older copy
            if (tid == 0) asm volatile("cp.async.bulk.wait_group 1;" ::: "memory");
            __syncthreads();
        }
        const int row = row0 + i * 4 + r;
        const float v = __ldg(values + row);
        buf[r * 256 + col] = make_float4(s4.x * v, s4.y * v, s4.z * v, s4.w * v);
        __syncthreads();
        if (tid == 0) {
            asm volatile("fence.proxy.async;" ::: "memory");
            const float* gdst = out + (size_t)(row0 + i * 4) * M_;
            asm volatile(
                "cp.async.bulk.global.shared::cta.bulk_group [%0], [%1], %2;"
                :: "l"(gdst), "r"(smem_u32(buf)), "r"(16384) : "memory");
            asm volatile("cp.async.bulk.commit_group;" ::: "memory");
        }
    }
    if (tid == 0) asm volatile("cp.async.bulk.wait_group 0;" ::: "memory");
}

extern "C" void kernel_launch(void* const* d_in, const int* in_sizes, int n_in,
                              void* d_out, int out_size) {
    // metadata order: queries, keys, values, W, b
    const float* keys   = (const float*)d_in[1];
    const float* values = (const float*)d_in[2];
    const float* W      = (const float*)d_in[3];
    const float* bias   = (const float*)d_in[4];
    float* out = (float*)d_out;

    k_fused<<<G_, 1024>>>(keys, values, W, bias, out);
}